// round 5
// baseline (speedup 1.0000x reference)
#include <cuda_runtime.h>
#include <cstdint>

// GraphSAGE, CSR-based (no atomics in the per-layer hot path):
//   once:  deg -> exclusive scan -> CSR col array (src per dst-sorted edge)
//   layer: fused [warp-per-node mean-gather into smem] + [reg-tiled dual GEMM]
//          x = relu((csr_mean_gather(x)) @ Wl^T + bl + x @ Wr^T)

#define NODES_MAX 100000
#define EDGES_MAX 1600000
#define DD 64
#define WPAD 68
#define NPAD 68
#define UPD_SMEM ((2*64*WPAD + 2*128*NPAD) * 4)   // 104448 bytes

__device__ float g_bufA[(size_t)NODES_MAX * DD];
__device__ float g_bufB[(size_t)NODES_MAX * DD];
__device__ float g_inv [NODES_MAX];
__device__ int   g_deg [NODES_MAX];
__device__ int   g_row [NODES_MAX];     // exclusive scan of deg
__device__ int   g_cur [NODES_MAX];     // build cursors
__device__ int   g_col [EDGES_MAX];     // src indices grouped by dst
__device__ int   g_bsum [512];
__device__ int   g_bsumex[512];
__device__ int   g_is64;

// --------------------------------------------------------------------------
__global__ void k_detect(const int* __restrict__ ei32) {
    int is64 = 1;
    #pragma unroll 1
    for (int i = 0; i < 64; ++i)
        if (ei32[2 * i + 1] != 0) { is64 = 0; break; }
    g_is64 = is64;
}

__device__ __forceinline__ int fetch_idx(const void* ei, long long pos, int is64) {
    if (is64) return (int)((const long long*)ei)[pos];
    return ((const int*)ei)[pos];
}

// --------------------------------------------------------------------------
__global__ void k_clear_deg(int n) {
    int i = blockIdx.x * blockDim.x + threadIdx.x;
    if (i < n) g_deg[i] = 0;
}

__global__ void k_deg(const void* __restrict__ ei, int E) {
    int e = blockIdx.x * blockDim.x + threadIdx.x;
    if (e >= E) return;
    int d = fetch_idx(ei, (long long)E + e, g_is64);
    atomicAdd(&g_deg[d], 1);
}

// Block-local exclusive scan (256/block) + per-block sums; also inv_deg.
__global__ void k_scan1(int n) {
    __shared__ int s[256];
    int tid = threadIdx.x;
    int v = blockIdx.x * 256 + tid;
    int d = (v < n) ? g_deg[v] : 0;
    s[tid] = d;
    __syncthreads();
    #pragma unroll
    for (int off = 1; off < 256; off <<= 1) {
        int t = (tid >= off) ? s[tid - off] : 0;
        __syncthreads();
        s[tid] += t;
        __syncthreads();
    }
    if (v < n) {
        g_row[v] = s[tid] - d;                   // exclusive within block
        g_inv[v] = 1.0f / (float)max(d, 1);
    }
    if (tid == 255) g_bsum[blockIdx.x] = s[255];
}

// Single-block exclusive scan of block sums (nb <= 512).
__global__ void k_scan2(int nb) {
    __shared__ int s[512];
    int tid = threadIdx.x;
    int d = (tid < nb) ? g_bsum[tid] : 0;
    s[tid] = d;
    __syncthreads();
    #pragma unroll
    for (int off = 1; off < 512; off <<= 1) {
        int t = (tid >= off) ? s[tid - off] : 0;
        __syncthreads();
        s[tid] += t;
        __syncthreads();
    }
    g_bsumex[tid] = s[tid] - d;
}

__global__ void k_scan3(int n) {
    int v = blockIdx.x * 256 + threadIdx.x;
    if (v < n) {
        int r = g_row[v] + g_bsumex[blockIdx.x];
        g_row[v] = r;
        g_cur[v] = r;
    }
}

__global__ void k_build(const void* __restrict__ ei, int E) {
    int e = blockIdx.x * blockDim.x + threadIdx.x;
    if (e >= E) return;
    int is64 = g_is64;
    int s = fetch_idx(ei, e, is64);
    int d = fetch_idx(ei, (long long)E + e, is64);
    int pos = atomicAdd(&g_cur[d], 1);
    g_col[pos] = s;
}

// --------------------------------------------------------------------------
// Fused layer: block = 128 nodes, 256 threads.
// Phase A: stage weights + root rows; warp-per-node CSR mean-gather -> sA.
// Phase B: reg-tiled GEMM: out = relu(sA@Wl^T + bl + sX@Wr^T).
// --------------------------------------------------------------------------
__global__ void __launch_bounds__(256, 2)
k_layer(const float* __restrict__ xin,
        const float* __restrict__ Wl, const float* __restrict__ bl,
        const float* __restrict__ Wr,
        float* __restrict__ xout, int n)
{
    extern __shared__ float smem[];
    float* sWl = smem;
    float* sWr = sWl + 64 * WPAD;
    float* sA  = sWr + 64 * WPAD;
    float* sX  = sA  + 128 * NPAD;

    const int tid  = threadIdx.x;
    const int base = blockIdx.x * 128;

    // Stage weights
    for (int idx = tid; idx < 64 * 16; idx += 256) {
        int r = idx >> 4, c = idx & 15;
        float4 wl = ((const float4*)Wl)[idx];
        float4 wr = ((const float4*)Wr)[idx];
        *(float4*)(sWl + r * WPAD + c * 4) = wl;
        *(float4*)(sWr + r * WPAD + c * 4) = wr;
    }
    // Stage root rows
    for (int idx = tid; idx < 128 * 16; idx += 256) {
        int v = idx >> 4, c = idx & 15;
        int vg = base + v;
        float4 xv = make_float4(0.f, 0.f, 0.f, 0.f);
        if (vg < n) xv = *(const float4*)(xin + (size_t)vg * 64 + c * 4);
        *(float4*)(sX + v * NPAD + c * 4) = xv;
    }

    // Warp-per-node mean gather. lane -> feature cols [2*lane, 2*lane+1].
    {
        const int warp = tid >> 5;
        const int lane = tid & 31;
        const float2* x2 = (const float2*)xin;
        #pragma unroll 1
        for (int nd = 0; nd < 16; ++nd) {
            int vl = warp * 16 + nd;
            int vg = base + vl;
            float2 acc = make_float2(0.f, 0.f);
            if (vg < n) {
                int rs = g_row[vg];
                int end = rs + g_deg[vg];
                int e = rs;
                for (; e + 4 <= end; e += 4) {
                    int s0 = g_col[e], s1 = g_col[e + 1];
                    int s2 = g_col[e + 2], s3 = g_col[e + 3];
                    float2 a0 = x2[(size_t)s0 * 32 + lane];
                    float2 a1 = x2[(size_t)s1 * 32 + lane];
                    float2 a2 = x2[(size_t)s2 * 32 + lane];
                    float2 a3 = x2[(size_t)s3 * 32 + lane];
                    acc.x += (a0.x + a1.x) + (a2.x + a3.x);
                    acc.y += (a0.y + a1.y) + (a2.y + a3.y);
                }
                for (; e < end; ++e) {
                    int s0 = g_col[e];
                    float2 a0 = x2[(size_t)s0 * 32 + lane];
                    acc.x += a0.x; acc.y += a0.y;
                }
                float iv = g_inv[vg];
                acc.x *= iv; acc.y *= iv;
            }
            *(float2*)(sA + vl * NPAD + lane * 2) = acc;
        }
    }
    __syncthreads();

    // GEMM: thread = 8 nodes x 4 output features
    const int ng = tid >> 4;
    const int jg = tid & 15;

    float acc[8][4];
    #pragma unroll
    for (int i = 0; i < 8; ++i)
        #pragma unroll
        for (int jj = 0; jj < 4; ++jj) acc[i][jj] = 0.f;

    #pragma unroll 1
    for (int k4 = 0; k4 < 16; ++k4) {
        float4 wl[4], wr[4];
        #pragma unroll
        for (int jj = 0; jj < 4; ++jj) {
            int j = jj * 16 + jg;
            wl[jj] = *(const float4*)(sWl + j * WPAD + k4 * 4);
            wr[jj] = *(const float4*)(sWr + j * WPAD + k4 * 4);
        }
        #pragma unroll
        for (int i = 0; i < 8; ++i) {
            int v = i * 16 + ng;
            float4 a  = *(const float4*)(sA + v * NPAD + k4 * 4);
            float4 xv = *(const float4*)(sX + v * NPAD + k4 * 4);
            #pragma unroll
            for (int jj = 0; jj < 4; ++jj) {
                acc[i][jj] += a.x  * wl[jj].x + a.y  * wl[jj].y
                            + a.z  * wl[jj].z + a.w  * wl[jj].w
                            + xv.x * wr[jj].x + xv.y * wr[jj].y
                            + xv.z * wr[jj].z + xv.w * wr[jj].w;
            }
        }
    }

    float bias[4];
    #pragma unroll
    for (int jj = 0; jj < 4; ++jj) bias[jj] = bl[jj * 16 + jg];

    #pragma unroll
    for (int i = 0; i < 8; ++i) {
        int vg = base + i * 16 + ng;
        if (vg < n) {
            #pragma unroll
            for (int jj = 0; jj < 4; ++jj) {
                int j = jj * 16 + jg;
                xout[(size_t)vg * 64 + j] = fmaxf(acc[i][jj] + bias[jj], 0.f);
            }
        }
    }
}

// --------------------------------------------------------------------------
extern "C" void kernel_launch(void* const* d_in, const int* in_sizes, int n_in,
                              void* d_out, int out_size)
{
    const float* x  = (const float*)d_in[0];
    const float* Wl = (const float*)d_in[1];
    const float* bl = (const float*)d_in[2];
    const float* Wr = (const float*)d_in[3];
    const void*  ei = d_in[4];

    const int n = in_sizes[0] / DD;
    const int E = in_sizes[4] / 2;
    const int L = in_sizes[1] / (DD * DD);

    float *bufA = nullptr, *bufB = nullptr;
    cudaGetSymbolAddress((void**)&bufA, g_bufA);
    cudaGetSymbolAddress((void**)&bufB, g_bufB);

    cudaFuncSetAttribute(k_layer, cudaFuncAttributeMaxDynamicSharedMemorySize,
                         UPD_SMEM);

    const int nb = (n + 255) / 256;   // 391 <= 512

    k_detect<<<1, 1>>>((const int*)ei);
    k_clear_deg<<<nb, 256>>>(n);
    k_deg<<<(E + 255) / 256, 256>>>(ei, E);
    k_scan1<<<nb, 256>>>(n);
    k_scan2<<<1, 512>>>(nb);
    k_scan3<<<nb, 256>>>(n);
    k_build<<<(E + 255) / 256, 256>>>(ei, E);

    const float* cur = x;
    for (int l = 0; l < L; ++l) {
        float* outp = (l == L - 1) ? (float*)d_out
                                   : ((l & 1) ? bufB : bufA);
        k_layer<<<(n + 127) / 128, 256, UPD_SMEM>>>(
            cur, Wl + (size_t)l * DD * DD, bl + (size_t)l * DD,
            Wr + (size_t)l * DD * DD, outp, n);
        cur = outp;
    }
}

// round 7
// speedup vs baseline: 1.1314x; 1.1314x over previous
#include <cuda_runtime.h>
#include <cstdint>

// GraphSAGE via CSR + fused layer:
//   pre:   deg -> 2-level exclusive scan -> CSR col build (scan-3 folded away)
//   layer: warp-per-node mean-gather (8-deep MLP) -> smem
//          reg-tiled dual GEMM using packed fma.rn.f32x2 (FFMA2)
//          x = relu(agg @ Wl^T + bl + x @ Wr^T)

#define NODES_MAX 100000
#define EDGES_MAX 1600000
#define DD 64
#define WTP 68            // transposed weight tile stride; mult of 4 for LDS.128
#define NPAD 68           // input tile row stride
#define UPD_SMEM ((2*64*WTP + 2*128*NPAD) * 4)   // 104448 bytes

__device__ float g_bufA[(size_t)NODES_MAX * DD];
__device__ float g_bufB[(size_t)NODES_MAX * DD];
__device__ float g_inv [NODES_MAX];
__device__ int   g_deg [NODES_MAX];
__device__ int   g_row [NODES_MAX];     // block-local exclusive scan of deg
__device__ int   g_cur [NODES_MAX];     // build cursors (block-local base)
__device__ int   g_col [EDGES_MAX];     // src indices grouped by dst
__device__ int   g_bsum  [512];
__device__ int   g_bsumex[512];         // exclusive scan of per-block sums
__device__ int   g_is64;

// ---------------------------------------------------------------------------
__device__ __forceinline__ int fetch_idx(const void* ei, long long pos, int is64) {
    if (is64) return (int)((const long long*)ei)[pos];
    return ((const int*)ei)[pos];
}

#define FFMA2(d, a, b) \
    asm("fma.rn.f32x2 %0, %1, %2, %0;" : "+l"(d) : "l"(a), "l"(b))
#define PACK2(d, lo, hi) \
    asm("mov.b64 %0, {%1, %2};" : "=l"(d) : "f"(lo), "f"(hi))
#define UNPACK2(lo, hi, s) \
    asm("mov.b64 {%0, %1}, %2;" : "=f"(lo), "=f"(hi) : "l"(s))

// ---------------------------------------------------------------------------
// launch 0: clear degrees; thread 0 also detects edge dtype.
__global__ void k_clear_detect(const int* __restrict__ ei32, int n) {
    int i = blockIdx.x * blockDim.x + threadIdx.x;
    if (i < n) g_deg[i] = 0;
    if (i == 0) {
        int is64 = 1;
        #pragma unroll 1
        for (int k = 0; k < 64; ++k)
            if (ei32[2 * k + 1] != 0) { is64 = 0; break; }
        g_is64 = is64;
    }
}

// launch 1
__global__ void k_deg(const void* __restrict__ ei, int E) {
    int e = blockIdx.x * blockDim.x + threadIdx.x;
    if (e >= E) return;
    int d = fetch_idx(ei, (long long)E + e, g_is64);
    atomicAdd(&g_deg[d], 1);
}

// launch 2: block-local exclusive scan + per-block sums + inv_deg
__global__ void k_scan1(int n) {
    __shared__ int s[256];
    int tid = threadIdx.x;
    int v = blockIdx.x * 256 + tid;
    int d = (v < n) ? g_deg[v] : 0;
    s[tid] = d;
    __syncthreads();
    #pragma unroll
    for (int off = 1; off < 256; off <<= 1) {
        int t = (tid >= off) ? s[tid - off] : 0;
        __syncthreads();
        s[tid] += t;
        __syncthreads();
    }
    if (v < n) {
        int r = s[tid] - d;
        g_row[v] = r;
        g_cur[v] = r;
        g_inv[v] = 1.0f / (float)max(d, 1);
    }
    if (tid == 255) g_bsum[blockIdx.x] = s[255];
}

// launch 3: exclusive scan of block sums (nb <= 512), one block
__global__ void k_scan2(int nb) {
    __shared__ int s[512];
    int tid = threadIdx.x;
    int d = (tid < nb) ? g_bsum[tid] : 0;
    s[tid] = d;
    __syncthreads();
    #pragma unroll
    for (int off = 1; off < 512; off <<= 1) {
        int t = (tid >= off) ? s[tid - off] : 0;
        __syncthreads();
        s[tid] += t;
        __syncthreads();
    }
    g_bsumex[tid] = s[tid] - d;
}

// launch 4: scatter src into CSR col (cursor = local + block offset)
__global__ void k_build(const void* __restrict__ ei, int E) {
    int e = blockIdx.x * blockDim.x + threadIdx.x;
    if (e >= E) return;
    int is64 = g_is64;
    int s = fetch_idx(ei, e, is64);
    int d = fetch_idx(ei, (long long)E + e, is64);
    int pos = atomicAdd(&g_cur[d], 1) + g_bsumex[d >> 8];
    g_col[pos] = s;
}

// ---------------------------------------------------------------------------
// Fused layer: 128 nodes / 256 threads per block.
//   Phase A: stage transposed weights + root rows; warp-per-node mean gather
//            with 8 independent loads in flight.
//   Phase B: thread = 8 nodes x 4 consecutive features, FFMA2 inner loop.
// ---------------------------------------------------------------------------
__global__ void __launch_bounds__(256, 2)
k_layer(const float* __restrict__ xin,
        const float* __restrict__ Wl, const float* __restrict__ bl,
        const float* __restrict__ Wr,
        float* __restrict__ xout, int n)
{
    extern __shared__ float smem[];
    float* sWl = smem;                 // transposed: [k][j], stride WTP
    float* sWr = sWl + 64 * WTP;
    float* sA  = sWr + 64 * WTP;       // [node][k], stride NPAD
    float* sX  = sA  + 128 * NPAD;

    const int tid  = threadIdx.x;
    const int base = blockIdx.x * 128;

    // Stage weights, transposing: W[j][k] -> sW[k*WTP + j]
    for (int idx = tid; idx < 64 * 16; idx += 256) {
        int j = idx >> 4, c = idx & 15;          // c: k/4
        float4 wl = ((const float4*)Wl)[idx];
        float4 wr = ((const float4*)Wr)[idx];
        int k0 = c * 4;
        sWl[(k0 + 0) * WTP + j] = wl.x;
        sWl[(k0 + 1) * WTP + j] = wl.y;
        sWl[(k0 + 2) * WTP + j] = wl.z;
        sWl[(k0 + 3) * WTP + j] = wl.w;
        sWr[(k0 + 0) * WTP + j] = wr.x;
        sWr[(k0 + 1) * WTP + j] = wr.y;
        sWr[(k0 + 2) * WTP + j] = wr.z;
        sWr[(k0 + 3) * WTP + j] = wr.w;
    }
    // Stage root rows
    for (int idx = tid; idx < 128 * 16; idx += 256) {
        int v = idx >> 4, c = idx & 15;
        int vg = base + v;
        float4 xv = make_float4(0.f, 0.f, 0.f, 0.f);
        if (vg < n) xv = *(const float4*)(xin + (size_t)vg * 64 + c * 4);
        *(float4*)(sX + v * NPAD + c * 4) = xv;
    }

    // Warp-per-node mean gather; lane owns cols [2*lane, 2*lane+1].
    {
        const int warp = tid >> 5;
        const int lane = tid & 31;
        const float2* x2 = (const float2*)xin;
        #pragma unroll 1
        for (int nd = 0; nd < 16; ++nd) {
            int vl = warp * 16 + nd;
            int vg = base + vl;
            float2 acc = make_float2(0.f, 0.f);
            if (vg < n) {
                int rs  = g_row[vg] + g_bsumex[vg >> 8];
                int end = rs + g_deg[vg];
                int e = rs;
                // 8 loads in flight
                for (; e + 8 <= end; e += 8) {
                    int s0 = g_col[e+0], s1 = g_col[e+1], s2 = g_col[e+2], s3 = g_col[e+3];
                    int s4 = g_col[e+4], s5 = g_col[e+5], s6 = g_col[e+6], s7 = g_col[e+7];
                    float2 a0 = x2[(size_t)s0*32 + lane], a1 = x2[(size_t)s1*32 + lane];
                    float2 a2 = x2[(size_t)s2*32 + lane], a3 = x2[(size_t)s3*32 + lane];
                    float2 a4 = x2[(size_t)s4*32 + lane], a5 = x2[(size_t)s5*32 + lane];
                    float2 a6 = x2[(size_t)s6*32 + lane], a7 = x2[(size_t)s7*32 + lane];
                    float px = ((a0.x + a1.x) + (a2.x + a3.x)) + ((a4.x + a5.x) + (a6.x + a7.x));
                    float py = ((a0.y + a1.y) + (a2.y + a3.y)) + ((a4.y + a5.y) + (a6.y + a7.y));
                    acc.x += px; acc.y += py;
                }
                for (; e + 4 <= end; e += 4) {
                    int s0 = g_col[e+0], s1 = g_col[e+1], s2 = g_col[e+2], s3 = g_col[e+3];
                    float2 a0 = x2[(size_t)s0*32 + lane], a1 = x2[(size_t)s1*32 + lane];
                    float2 a2 = x2[(size_t)s2*32 + lane], a3 = x2[(size_t)s3*32 + lane];
                    acc.x += (a0.x + a1.x) + (a2.x + a3.x);
                    acc.y += (a0.y + a1.y) + (a2.y + a3.y);
                }
                for (; e < end; ++e) {
                    float2 a0 = x2[(size_t)g_col[e]*32 + lane];
                    acc.x += a0.x; acc.y += a0.y;
                }
                float iv = g_inv[vg];
                acc.x *= iv; acc.y *= iv;
            }
            *(float2*)(sA + vl * NPAD + lane * 2) = acc;
        }
    }
    __syncthreads();

    // GEMM: thread = 8 nodes (i*16+ng) x 4 consecutive features (4*jg..4*jg+3)
    const int ng = tid >> 4;
    const int jg = tid & 15;
    const int j0 = jg * 4;

    unsigned long long acc2[8][2];
    #pragma unroll
    for (int i = 0; i < 8; ++i) { acc2[i][0] = 0ull; acc2[i][1] = 0ull; }

    #pragma unroll 1
    for (int k4 = 0; k4 < 16; ++k4) {
        int k0 = k4 * 4;
        // weight pairs for this thread's 4 features, 4 ks, both matrices
        unsigned long long wl2[4][2], wr2[4][2];
        #pragma unroll
        for (int q = 0; q < 4; ++q) {
            float4 wl = *(const float4*)(sWl + (k0 + q) * WTP + j0);
            float4 wr = *(const float4*)(sWr + (k0 + q) * WTP + j0);
            PACK2(wl2[q][0], wl.x, wl.y);
            PACK2(wl2[q][1], wl.z, wl.w);
            PACK2(wr2[q][0], wr.x, wr.y);
            PACK2(wr2[q][1], wr.z, wr.w);
        }
        #pragma unroll
        for (int i = 0; i < 8; ++i) {
            int v = i * 16 + ng;
            float4 a  = *(const float4*)(sA + v * NPAD + k0);
            float4 xv = *(const float4*)(sX + v * NPAD + k0);
            unsigned long long aa, xx;
            PACK2(aa, a.x, a.x);  PACK2(xx, xv.x, xv.x);
            FFMA2(acc2[i][0], wl2[0][0], aa); FFMA2(acc2[i][1], wl2[0][1], aa);
            FFMA2(acc2[i][0], wr2[0][0], xx); FFMA2(acc2[i][1], wr2[0][1], xx);
            PACK2(aa, a.y, a.y);  PACK2(xx, xv.y, xv.y);
            FFMA2(acc2[i][0], wl2[1][0], aa); FFMA2(acc2[i][1], wl2[1][1], aa);
            FFMA2(acc2[i][0], wr2[1][0], xx); FFMA2(acc2[i][1], wr2[1][1], xx);
            PACK2(aa, a.z, a.z);  PACK2(xx, xv.z, xv.z);
            FFMA2(acc2[i][0], wl2[2][0], aa); FFMA2(acc2[i][1], wl2[2][1], aa);
            FFMA2(acc2[i][0], wr2[2][0], xx); FFMA2(acc2[i][1], wr2[2][1], xx);
            PACK2(aa, a.w, a.w);  PACK2(xx, xv.w, xv.w);
            FFMA2(acc2[i][0], wl2[3][0], aa); FFMA2(acc2[i][1], wl2[3][1], aa);
            FFMA2(acc2[i][0], wr2[3][0], xx); FFMA2(acc2[i][1], wr2[3][1], xx);
        }
    }

    float4 bias = *(const float4*)(bl + j0);

    #pragma unroll
    for (int i = 0; i < 8; ++i) {
        int vg = base + i * 16 + ng;
        if (vg < n) {
            float4 o;
            float lo, hi;
            UNPACK2(lo, hi, acc2[i][0]); o.x = lo; o.y = hi;
            UNPACK2(lo, hi, acc2[i][1]); o.z = lo; o.w = hi;
            o.x = fmaxf(o.x + bias.x, 0.f);
            o.y = fmaxf(o.y + bias.y, 0.f);
            o.z = fmaxf(o.z + bias.z, 0.f);
            o.w = fmaxf(o.w + bias.w, 0.f);
            *(float4*)(xout + (size_t)vg * 64 + j0) = o;
        }
    }
}

// ---------------------------------------------------------------------------
extern "C" void kernel_launch(void* const* d_in, const int* in_sizes, int n_in,
                              void* d_out, int out_size)
{
    const float* x  = (const float*)d_in[0];
    const float* Wl = (const float*)d_in[1];
    const float* bl = (const float*)d_in[2];
    const float* Wr = (const float*)d_in[3];
    const void*  ei = d_in[4];

    const int n = in_sizes[0] / DD;
    const int E = in_sizes[4] / 2;
    const int L = in_sizes[1] / (DD * DD);

    float *bufA = nullptr, *bufB = nullptr;
    cudaGetSymbolAddress((void**)&bufA, g_bufA);
    cudaGetSymbolAddress((void**)&bufB, g_bufB);

    cudaFuncSetAttribute(k_layer, cudaFuncAttributeMaxDynamicSharedMemorySize,
                         UPD_SMEM);

    const int nb = (n + 255) / 256;   // 391 <= 512

    // 5 preprocessing launches so ncu (-s 5) profiles the first k_layer.
    k_clear_detect<<<nb, 256>>>((const int*)ei, n);          // 0
    k_deg<<<(E + 255) / 256, 256>>>(ei, E);                  // 1
    k_scan1<<<nb, 256>>>(n);                                 // 2
    k_scan2<<<1, 512>>>(nb);                                 // 3
    k_build<<<(E + 255) / 256, 256>>>(ei, E);                // 4

    const float* cur = x;
    for (int l = 0; l < L; ++l) {
        float* outp = (l == L - 1) ? (float*)d_out
                                   : ((l & 1) ? bufB : bufA);
        k_layer<<<(n + 127) / 128, 256, UPD_SMEM>>>(
            cur, Wl + (size_t)l * DD * DD, bl + (size_t)l * DD,
            Wr + (size_t)l * DD * DD, outp, n);
        cur = outp;
    }
}

// round 9
// speedup vs baseline: 1.5429x; 1.3637x over previous
#include <cuda_runtime.h>
#include <cstdint>

// GraphSAGE via CSR, split per-layer kernels:
//   pre:     deg -> 2-level exclusive scan -> CSR col build
//   gather:  warp-per-node mean-gather (high occupancy, LTS-bound) -> g_agg
//   gemm:    reg-tiled dual GEMM, 8 nodes x 8 features / thread, FFMA2
//            x = relu(agg @ Wl^T + bl + x @ Wr^T)

#define NODES_MAX 100000
#define EDGES_MAX 1600000
#define DD 64
#define WTP 68            // transposed weight tile stride (mult of 4)
#define NPAD 68           // input tile row stride (mult of 4)
#define GEMM_SMEM ((2*64*WTP + 2*128*NPAD) * 4)   // 104448 bytes

__device__ float g_agg [(size_t)NODES_MAX * DD];
__device__ float g_bufA[(size_t)NODES_MAX * DD];
__device__ float g_bufB[(size_t)NODES_MAX * DD];
__device__ float g_inv [NODES_MAX];
__device__ int   g_deg [NODES_MAX];
__device__ int   g_row [NODES_MAX];     // block-local exclusive scan of deg
__device__ int   g_cur [NODES_MAX];     // build cursors (block-local base)
__device__ int   g_col [EDGES_MAX];     // src indices grouped by dst
__device__ int   g_bsum  [512];
__device__ int   g_bsumex[512];         // exclusive scan of per-block sums
__device__ int   g_is64;

// ---------------------------------------------------------------------------
__device__ __forceinline__ int fetch_idx(const void* ei, long long pos, int is64) {
    if (is64) return (int)((const long long*)ei)[pos];
    return ((const int*)ei)[pos];
}

#define FFMA2(d, a, b) \
    asm("fma.rn.f32x2 %0, %1, %2, %0;" : "+l"(d) : "l"(a), "l"(b))
#define PACK2(d, lo, hi) \
    asm("mov.b64 %0, {%1, %2};" : "=l"(d) : "f"(lo), "f"(hi))
#define UNPACK2(lo, hi, s) \
    asm("mov.b64 {%0, %1}, %2;" : "=f"(lo), "=f"(hi) : "l"(s))

// ---------------------------------------------------------------------------
// launch 0: clear degrees; thread 0 also detects edge dtype.
__global__ void k_clear_detect(const int* __restrict__ ei32, int n) {
    int i = blockIdx.x * blockDim.x + threadIdx.x;
    if (i < n) g_deg[i] = 0;
    if (i == 0) {
        int is64 = 1;
        #pragma unroll 1
        for (int k = 0; k < 64; ++k)
            if (ei32[2 * k + 1] != 0) { is64 = 0; break; }
        g_is64 = is64;
    }
}

// launch 1
__global__ void k_deg(const void* __restrict__ ei, int E) {
    int e = blockIdx.x * blockDim.x + threadIdx.x;
    if (e >= E) return;
    int d = fetch_idx(ei, (long long)E + e, g_is64);
    atomicAdd(&g_deg[d], 1);
}

// launch 2: block-local exclusive scan + per-block sums + inv_deg
__global__ void k_scan1(int n) {
    __shared__ int s[256];
    int tid = threadIdx.x;
    int v = blockIdx.x * 256 + tid;
    int d = (v < n) ? g_deg[v] : 0;
    s[tid] = d;
    __syncthreads();
    #pragma unroll
    for (int off = 1; off < 256; off <<= 1) {
        int t = (tid >= off) ? s[tid - off] : 0;
        __syncthreads();
        s[tid] += t;
        __syncthreads();
    }
    if (v < n) {
        int r = s[tid] - d;
        g_row[v] = r;
        g_cur[v] = r;
        g_inv[v] = 1.0f / (float)max(d, 1);
    }
    if (tid == 255) g_bsum[blockIdx.x] = s[255];
}

// launch 3: exclusive scan of block sums (nb <= 512), one block
__global__ void k_scan2(int nb) {
    __shared__ int s[512];
    int tid = threadIdx.x;
    int d = (tid < nb) ? g_bsum[tid] : 0;
    s[tid] = d;
    __syncthreads();
    #pragma unroll
    for (int off = 1; off < 512; off <<= 1) {
        int t = (tid >= off) ? s[tid - off] : 0;
        __syncthreads();
        s[tid] += t;
        __syncthreads();
    }
    g_bsumex[tid] = s[tid] - d;
}

// launch 4: scatter src into CSR col (cursor = local + block offset)
__global__ void k_build(const void* __restrict__ ei, int E) {
    int e = blockIdx.x * blockDim.x + threadIdx.x;
    if (e >= E) return;
    int is64 = g_is64;
    int s = fetch_idx(ei, e, is64);
    int d = fetch_idx(ei, (long long)E + e, is64);
    int pos = atomicAdd(&g_cur[d], 1) + g_bsumex[d >> 8];
    g_col[pos] = s;
}

// ---------------------------------------------------------------------------
// Gather: warp per node, lane owns feature cols [2*lane, 2*lane+1].
// High occupancy (no smem), 8 row-loads in flight -> LTS-bound.
// Writes mean (inv pre-multiplied) into g_agg.
// ---------------------------------------------------------------------------
__global__ void __launch_bounds__(256)
k_gather(const float* __restrict__ xin, int n)
{
    int gw   = (blockIdx.x * blockDim.x + threadIdx.x) >> 5;
    int lane = threadIdx.x & 31;
    if (gw >= n) return;
    const int v = gw;

    const float2* x2 = (const float2*)xin;
    float2 acc = make_float2(0.f, 0.f);

    int rs  = g_row[v] + g_bsumex[v >> 8];
    int end = rs + g_deg[v];
    int e = rs;
    for (; e + 8 <= end; e += 8) {
        int s0 = g_col[e+0], s1 = g_col[e+1], s2 = g_col[e+2], s3 = g_col[e+3];
        int s4 = g_col[e+4], s5 = g_col[e+5], s6 = g_col[e+6], s7 = g_col[e+7];
        float2 a0 = x2[(size_t)s0*32 + lane], a1 = x2[(size_t)s1*32 + lane];
        float2 a2 = x2[(size_t)s2*32 + lane], a3 = x2[(size_t)s3*32 + lane];
        float2 a4 = x2[(size_t)s4*32 + lane], a5 = x2[(size_t)s5*32 + lane];
        float2 a6 = x2[(size_t)s6*32 + lane], a7 = x2[(size_t)s7*32 + lane];
        acc.x += ((a0.x + a1.x) + (a2.x + a3.x)) + ((a4.x + a5.x) + (a6.x + a7.x));
        acc.y += ((a0.y + a1.y) + (a2.y + a3.y)) + ((a4.y + a5.y) + (a6.y + a7.y));
    }
    for (; e + 4 <= end; e += 4) {
        int s0 = g_col[e+0], s1 = g_col[e+1], s2 = g_col[e+2], s3 = g_col[e+3];
        float2 a0 = x2[(size_t)s0*32 + lane], a1 = x2[(size_t)s1*32 + lane];
        float2 a2 = x2[(size_t)s2*32 + lane], a3 = x2[(size_t)s3*32 + lane];
        acc.x += (a0.x + a1.x) + (a2.x + a3.x);
        acc.y += (a0.y + a1.y) + (a2.y + a3.y);
    }
    for (; e < end; ++e) {
        float2 a0 = x2[(size_t)g_col[e]*32 + lane];
        acc.x += a0.x; acc.y += a0.y;
    }
    float iv = g_inv[v];
    acc.x *= iv; acc.y *= iv;
    *(float2*)(g_agg + (size_t)v * 64 + lane * 2) = acc;
}

// ---------------------------------------------------------------------------
// GEMM: 128 nodes / 128 threads per block; thread = 8 nodes x 8 features.
// out = relu(agg @ Wl^T + bl + x @ Wr^T), FFMA2 inner loop.
// ---------------------------------------------------------------------------
__global__ void __launch_bounds__(128, 2)
k_gemm(const float* __restrict__ xin,
       const float* __restrict__ Wl, const float* __restrict__ bl,
       const float* __restrict__ Wr,
       float* __restrict__ xout, int n)
{
    extern __shared__ float smem[];
    float* sWl = smem;                 // transposed: [k][j], stride WTP
    float* sWr = sWl + 64 * WTP;
    float* sA  = sWr + 64 * WTP;       // [node][k], stride NPAD
    float* sX  = sA  + 128 * NPAD;

    const int tid  = threadIdx.x;
    const int base = blockIdx.x * 128;

    // Stage weights, transposing: W[j][k] -> sW[k*WTP + j]
    for (int idx = tid; idx < 64 * 16; idx += 128) {
        int j = idx >> 4, c = idx & 15;
        float4 wl = ((const float4*)Wl)[idx];
        float4 wr = ((const float4*)Wr)[idx];
        int k0 = c * 4;
        sWl[(k0 + 0) * WTP + j] = wl.x;
        sWl[(k0 + 1) * WTP + j] = wl.y;
        sWl[(k0 + 2) * WTP + j] = wl.z;
        sWl[(k0 + 3) * WTP + j] = wl.w;
        sWr[(k0 + 0) * WTP + j] = wr.x;
        sWr[(k0 + 1) * WTP + j] = wr.y;
        sWr[(k0 + 2) * WTP + j] = wr.z;
        sWr[(k0 + 3) * WTP + j] = wr.w;
    }
    // Stage agg + root rows
    for (int idx = tid; idx < 128 * 16; idx += 128) {
        int v = idx >> 4, c = idx & 15;
        int vg = base + v;
        float4 a  = make_float4(0.f, 0.f, 0.f, 0.f);
        float4 xv = a;
        if (vg < n) {
            a  = *(const float4*)(g_agg + (size_t)vg * 64 + c * 4);
            xv = *(const float4*)(xin   + (size_t)vg * 64 + c * 4);
        }
        *(float4*)(sA + v * NPAD + c * 4) = a;
        *(float4*)(sX + v * NPAD + c * 4) = xv;
    }
    __syncthreads();

    const int ng = tid & 15;       // node group (low bits -> conflict-free LDS)
    const int jg = tid >> 4;       // 0..7
    const int j0 = jg * 8;

    unsigned long long acc2[8][4];
    #pragma unroll
    for (int i = 0; i < 8; ++i)
        #pragma unroll
        for (int p = 0; p < 4; ++p) acc2[i][p] = 0ull;

    #pragma unroll 1
    for (int k2 = 0; k2 < 32; ++k2) {
        int k0 = k2 * 2;
        // weights for 2 ks x 8 feats x 2 mats as ulonglong2 (pairs (j,j+1))
        ulonglong2 wl0a = *(const ulonglong2*)(sWl + (k0+0) * WTP + j0);
        ulonglong2 wl0b = *(const ulonglong2*)(sWl + (k0+0) * WTP + j0 + 4);
        ulonglong2 wl1a = *(const ulonglong2*)(sWl + (k0+1) * WTP + j0);
        ulonglong2 wl1b = *(const ulonglong2*)(sWl + (k0+1) * WTP + j0 + 4);
        ulonglong2 wr0a = *(const ulonglong2*)(sWr + (k0+0) * WTP + j0);
        ulonglong2 wr0b = *(const ulonglong2*)(sWr + (k0+0) * WTP + j0 + 4);
        ulonglong2 wr1a = *(const ulonglong2*)(sWr + (k0+1) * WTP + j0);
        ulonglong2 wr1b = *(const ulonglong2*)(sWr + (k0+1) * WTP + j0 + 4);

        #pragma unroll
        for (int i = 0; i < 8; ++i) {
            int v = i * 16 + ng;
            float2 a  = *(const float2*)(sA + v * NPAD + k0);
            float2 xv = *(const float2*)(sX + v * NPAD + k0);
            unsigned long long b;
            PACK2(b, a.x, a.x);
            FFMA2(acc2[i][0], wl0a.x, b); FFMA2(acc2[i][1], wl0a.y, b);
            FFMA2(acc2[i][2], wl0b.x, b); FFMA2(acc2[i][3], wl0b.y, b);
            PACK2(b, a.y, a.y);
            FFMA2(acc2[i][0], wl1a.x, b); FFMA2(acc2[i][1], wl1a.y, b);
            FFMA2(acc2[i][2], wl1b.x, b); FFMA2(acc2[i][3], wl1b.y, b);
            PACK2(b, xv.x, xv.x);
            FFMA2(acc2[i][0], wr0a.x, b); FFMA2(acc2[i][1], wr0a.y, b);
            FFMA2(acc2[i][2], wr0b.x, b); FFMA2(acc2[i][3], wr0b.y, b);
            PACK2(b, xv.y, xv.y);
            FFMA2(acc2[i][0], wr1a.x, b); FFMA2(acc2[i][1], wr1a.y, b);
            FFMA2(acc2[i][2], wr1b.x, b); FFMA2(acc2[i][3], wr1b.y, b);
        }
    }

    float4 bias0 = *(const float4*)(bl + j0);
    float4 bias1 = *(const float4*)(bl + j0 + 4);

    #pragma unroll
    for (int i = 0; i < 8; ++i) {
        int vg = base + i * 16 + ng;
        if (vg < n) {
            float4 o0, o1;
            float lo, hi;
            UNPACK2(lo, hi, acc2[i][0]); o0.x = lo; o0.y = hi;
            UNPACK2(lo, hi, acc2[i][1]); o0.z = lo; o0.w = hi;
            UNPACK2(lo, hi, acc2[i][2]); o1.x = lo; o1.y = hi;
            UNPACK2(lo, hi, acc2[i][3]); o1.z = lo; o1.w = hi;
            o0.x = fmaxf(o0.x + bias0.x, 0.f);
            o0.y = fmaxf(o0.y + bias0.y, 0.f);
            o0.z = fmaxf(o0.z + bias0.z, 0.f);
            o0.w = fmaxf(o0.w + bias0.w, 0.f);
            o1.x = fmaxf(o1.x + bias1.x, 0.f);
            o1.y = fmaxf(o1.y + bias1.y, 0.f);
            o1.z = fmaxf(o1.z + bias1.z, 0.f);
            o1.w = fmaxf(o1.w + bias1.w, 0.f);
            *(float4*)(xout + (size_t)vg * 64 + j0)     = o0;
            *(float4*)(xout + (size_t)vg * 64 + j0 + 4) = o1;
        }
    }
}

// ---------------------------------------------------------------------------
extern "C" void kernel_launch(void* const* d_in, const int* in_sizes, int n_in,
                              void* d_out, int out_size)
{
    const float* x  = (const float*)d_in[0];
    const float* Wl = (const float*)d_in[1];
    const float* bl = (const float*)d_in[2];
    const float* Wr = (const float*)d_in[3];
    const void*  ei = d_in[4];

    const int n = in_sizes[0] / DD;
    const int E = in_sizes[4] / 2;
    const int L = in_sizes[1] / (DD * DD);

    float *bufA = nullptr, *bufB = nullptr;
    cudaGetSymbolAddress((void**)&bufA, g_bufA);
    cudaGetSymbolAddress((void**)&bufB, g_bufB);

    cudaFuncSetAttribute(k_gemm, cudaFuncAttributeMaxDynamicSharedMemorySize,
                         GEMM_SMEM);

    const int nb = (n + 255) / 256;   // 391 <= 512

    // 5 preprocessing launches so ncu (-s 5) profiles the first k_gather.
    k_clear_detect<<<nb, 256>>>((const int*)ei, n);          // 0
    k_deg<<<(E + 255) / 256, 256>>>(ei, E);                  // 1
    k_scan1<<<nb, 256>>>(n);                                 // 2
    k_scan2<<<1, 512>>>(nb);                                 // 3
    k_build<<<(E + 255) / 256, 256>>>(ei, E);                // 4

    const float* cur = x;
    for (int l = 0; l < L; ++l) {
        float* outp = (l == L - 1) ? (float*)d_out
                                   : ((l & 1) ? bufB : bufA);
        int gwarps = n;                                  // one warp per node
        int gblocks = (gwarps * 32 + 255) / 256;
        k_gather<<<gblocks, 256>>>(cur, n);
        k_gemm<<<(n + 127) / 128, 128, GEMM_SMEM>>>(
            cur, Wl + (size_t)l * DD * DD, bl + (size_t)l * DD,
            Wr + (size_t)l * DD * DD, outp, n);
        cur = outp;
    }
}